// round 8
// baseline (speedup 1.0000x reference)
#include <cuda_runtime.h>
#include <math.h>

#define N_STATES      25
#define LUT_PITCH     65    // odd pitch: spreads banks for both the build STS and the gather LDS
#define LUT_ROWS      24    // states 1..24 (row 0 bookend is computed in ALU)
#define BLOCK_THREADS 256

// Fused kernel: warp-0 lanes 0..23 build the 24x64 NB log-pmf table via the
// recurrence  nb(x) = nb(x-1) + log((phi+x-1)/x) + log(mu/(phi+mu)),
// then all threads gather: out[s][i] = lut[s][obs[i]].
// One int4 group (4 spots) per thread, deep oversubscription (~26 blocks/SM
// queued) — the configuration that measured fastest (R6).
__global__ void __launch_bounds__(BLOCK_THREADS, 8)
emit_kernel(const float* __restrict__ means,
            const float* __restrict__ phis,
            const int*   __restrict__ obs,
            float*       __restrict__ out,
            int n_groups,        // n_spots / 4
            long long n_spots) {
    __shared__ float lut[LUT_ROWS * LUT_PITCH];

    if (threadIdx.x < LUT_ROWS) {
        int s = threadIdx.x + 1;                 // state 1..24
        float mu  = means[s];
        float phi = phis[s];
        float inv = 1.0f / (phi + mu);
        float c   = logf(mu * inv);              // log(mu/(phi+mu))
        float acc = phi * logf(phi * inv);       // nb(0)
        float* row = lut + threadIdx.x * LUT_PITCH;
        row[0] = acc;
        #pragma unroll 1
        for (int x = 1; x < 64; x++) {
            acc += c + logf((phi + (float)(x - 1)) / (float)x);
            row[x] = acc;
        }
        row[64] = 0.0f;                          // pad
    }
    __syncthreads();

    int g = blockIdx.x * BLOCK_THREADS + threadIdx.x;
    if (g >= n_groups) return;

    int4 o = ((const int4*)obs)[g];

    // Row 0: bookend, pure ALU (no smem traffic).
    {
        float4 v;
        v.x = (o.x > 0) ? -100000.0f : 0.0f;
        v.y = (o.y > 0) ? -100000.0f : 0.0f;
        v.z = (o.z > 0) ? -100000.0f : 0.0f;
        v.w = (o.w > 0) ? -100000.0f : 0.0f;
        ((float4*)out)[g] = v;
    }

    #pragma unroll
    for (int s = 1; s < N_STATES; s++) {
        const float* row = lut + (s - 1) * LUT_PITCH;
        float4 v;
        v.x = row[o.x];
        v.y = row[o.y];
        v.z = row[o.z];
        v.w = row[o.w];
        ((float4*)(out + (long long)s * n_spots))[g] = v;
    }
}

// Scalar fallback only if n_spots % 4 != 0 (never hit for N_SPOTS=4M).
// Rare path: compute directly with lgammaf.
__global__ void emit_tail_kernel(const float* __restrict__ means,
                                 const float* __restrict__ phis,
                                 const int*   __restrict__ obs,
                                 float*       __restrict__ out,
                                 int tail_start, int n_spots_i,
                                 long long n_spots) {
    int i = tail_start + blockIdx.x * blockDim.x + threadIdx.x;
    if (i >= n_spots_i) return;
    int x = obs[i];
    float xf = (float)x;
    out[i] = (x > 0) ? -100000.0f : 0.0f;
    for (int s = 1; s < N_STATES; s++) {
        float mu  = means[s];
        float phi = phis[s];
        float inv = 1.0f / (phi + mu);
        float v = lgammaf(xf + phi) - lgammaf(phi) - lgammaf(xf + 1.0f)
                + phi * logf(phi * inv)
                + xf  * logf(mu  * inv);
        out[(long long)s * n_spots + i] = v;
    }
}

extern "C" void kernel_launch(void* const* d_in, const int* in_sizes, int n_in,
                              void* d_out, int out_size) {
    const float* state_means = (const float*)d_in[0];
    const float* state_phis  = (const float*)d_in[1];
    const int*   obs         = (const int*)d_in[2];
    float*       out         = (float*)d_out;

    int n_spots_i = in_sizes[2];
    long long n_spots = (long long)n_spots_i;

    int n_groups = n_spots_i / 4;
    if (n_groups > 0) {
        int blocks = (n_groups + BLOCK_THREADS - 1) / BLOCK_THREADS;
        emit_kernel<<<blocks, BLOCK_THREADS>>>(state_means, state_phis, obs,
                                               out, n_groups, n_spots);
    }

    int tail_start = n_groups * 4;
    int tail = n_spots_i - tail_start;
    if (tail > 0) {
        emit_tail_kernel<<<(tail + 255) / 256, 256>>>(state_means, state_phis,
                                                      obs, out, tail_start,
                                                      n_spots_i, n_spots);
    }
}